// round 1
// baseline (speedup 1.0000x reference)
#include <cuda_runtime.h>
#include <math.h>

#define NL   8
#define D_   768
#define E_   1536
#define N_   16
#define K_   4
#define DTR_ 48
#define B_   2
#define L_   2048
#define SSMW (DTR_ + 2*N_)   /* 80 */
#define ML   (B_*L_)         /* 4096 rows */

// ---------------- static scratch (no allocations allowed) ----------------
__device__ float g_h   [ML * D_];        // residual stream
__device__ float g_hn  [ML * D_];        // rmsnorm output
__device__ float g_proj[ML * 2 * E_];    // in_proj output (u_raw | gate)
__device__ float g_u   [ML * E_];        // conv+silu output
__device__ float g_ssm [ML * SSMW];      // x_proj output (dt_r | B | C)
__device__ float g_dt  [ML * E_];        // softplus(dt)
__device__ float g_y   [ML * E_];        // scan output (gated)

// ---------------- RMSNorm: one block per row (D=768 = 256*3) -------------
__global__ void rmsnorm_kernel(const float* __restrict__ in,
                               const float* __restrict__ w,
                               float* __restrict__ out)
{
    int row = blockIdx.x;
    const float* x = in + (size_t)row * D_;
    float* o       = out + (size_t)row * D_;
    int t = threadIdx.x;               // 256 threads
    float v[3];
    float s = 0.f;
    #pragma unroll
    for (int i = 0; i < 3; i++) {
        v[i] = x[t + i * 256];
        s += v[i] * v[i];
    }
    __shared__ float red[256];
    red[t] = s;
    __syncthreads();
    #pragma unroll
    for (int off = 128; off > 0; off >>= 1) {
        if (t < off) red[t] += red[t + off];
        __syncthreads();
    }
    float scale = rsqrtf(red[0] * (1.0f / D_) + 1e-5f);
    #pragma unroll
    for (int i = 0; i < 3; i++) {
        int d = t + i * 256;
        o[d] = v[i] * scale * w[d];
    }
}

// ---------------- Generic NT SGEMM: C[M,N] = A[M,K] * B[N,K]^T -----------
// modes: 0 = store, 1 = softplus(acc + bias[n]), 2 = C += acc (residual add)
// Requires K % 16 == 0 (holds: 768, 1536, 48).
#define BM 64
#define BN 64
#define BK 16

__global__ void __launch_bounds__(256)
gemm_nt(const float* __restrict__ A, int lda,
        const float* __restrict__ Bw, int ldb,
        float* __restrict__ C, int ldc,
        int M, int N, int Kd,
        int mode, const float* __restrict__ bias)
{
    __shared__ __align__(16) float As[BK][BM + 4];
    __shared__ __align__(16) float Bs[BK][BN + 4];

    int bm = blockIdx.y * BM;
    int bn = blockIdx.x * BN;
    int tid = threadIdx.x;
    int tm = (tid / 16) * 4;       // 0..60
    int tn = (tid % 16) * 4;       // 0..60
    int lk = tid % 16;             // k within tile (coalesced global loads)
    int lm = tid / 16;             // 0..15

    float acc[4][4] = {};

    for (int k0 = 0; k0 < Kd; k0 += BK) {
        #pragma unroll
        for (int i = 0; i < 4; i++) {
            int m  = lm + i * 16;
            int gm = bm + m;
            As[lk][m] = (gm < M) ? A[(size_t)gm * lda + k0 + lk] : 0.f;
            int n  = lm + i * 16;
            int gn = bn + n;
            Bs[lk][n] = (gn < N) ? Bw[(size_t)gn * ldb + k0 + lk] : 0.f;
        }
        __syncthreads();

        #pragma unroll
        for (int kk = 0; kk < BK; kk++) {
            float4 a4 = *reinterpret_cast<const float4*>(&As[kk][tm]);
            float4 b4 = *reinterpret_cast<const float4*>(&Bs[kk][tn]);
            float a[4] = {a4.x, a4.y, a4.z, a4.w};
            float b[4] = {b4.x, b4.y, b4.z, b4.w};
            #pragma unroll
            for (int i = 0; i < 4; i++)
                #pragma unroll
                for (int j = 0; j < 4; j++)
                    acc[i][j] += a[i] * b[j];
        }
        __syncthreads();
    }

    #pragma unroll
    for (int i = 0; i < 4; i++) {
        int gm = bm + tm + i;
        if (gm >= M) continue;
        #pragma unroll
        for (int j = 0; j < 4; j++) {
            int gn = bn + tn + j;
            if (gn >= N) continue;
            float v = acc[i][j];
            size_t off = (size_t)gm * ldc + gn;
            if (mode == 1) {
                v += bias[gn];
                v = (v > 20.f) ? v : log1pf(__expf(v));  // softplus
                C[off] = v;
            } else if (mode == 2) {
                C[off] += v;
            } else {
                C[off] = v;
            }
        }
    }
}

// ---------------- causal depthwise conv (K=4) + SiLU ---------------------
__global__ void conv_silu_kernel(const float* __restrict__ proj,
                                 const float* __restrict__ cw,
                                 const float* __restrict__ cb,
                                 float* __restrict__ u)
{
    int idx = blockIdx.x * blockDim.x + threadIdx.x;
    if (idx >= ML * E_) return;
    int e = idx % E_;
    int r = idx / E_;          // r = b*L + l
    int l = r % L_;
    float acc = cb[e];
    #pragma unroll
    for (int j = 0; j < K_; j++) {
        int t = l - (K_ - 1) + j;
        if (t >= 0)
            acc += proj[(size_t)(r - (K_ - 1) + j) * (2 * E_) + e] * cw[e * K_ + j];
    }
    u[idx] = acc / (1.f + __expf(-acc));   // silu
}

// ---------------- selective scan: 16-lane group per (b,e) ----------------
// lane n keeps state s[n]; dA = exp(dt*A[n]); y_t = sum_n s[n]*C[n]
// Fuses D-skip and SiLU gating into the output.
__global__ void scan_kernel(const float* __restrict__ dtb,
                            const float* __restrict__ ssm,
                            const float* __restrict__ ub,
                            const float* __restrict__ proj,
                            const float* __restrict__ A_log,
                            const float* __restrict__ Dsk,
                            float* __restrict__ y)
{
    int g = blockIdx.x * (blockDim.x / 16) + (threadIdx.x / 16);
    int lane = threadIdx.x & 15;
    if (g >= B_ * E_) return;
    int b = g / E_;
    int e = g % E_;

    float A  = -__expf(A_log[e * N_ + lane]);
    float Dp = Dsk[e];
    float s  = 0.f;

    size_t base_be = (size_t)b * L_ * E_ + e;
    size_t base_bs = (size_t)b * L_ * SSMW;

    for (int t = 0; t < L_; t++) {
        size_t off = base_be + (size_t)t * E_;
        float dt = dtb[off];
        float uu = ub[off];
        const float* sp = ssm + base_bs + (size_t)t * SSMW;
        float Bv = sp[DTR_ + lane];
        float Cv = sp[DTR_ + N_ + lane];

        float dA = __expf(dt * A);
        s = s * dA + dt * Bv * uu;

        float p = s * Cv;
        p += __shfl_xor_sync(0xffffffffu, p, 8, 16);
        p += __shfl_xor_sync(0xffffffffu, p, 4, 16);
        p += __shfl_xor_sync(0xffffffffu, p, 2, 16);
        p += __shfl_xor_sync(0xffffffffu, p, 1, 16);

        if (lane == 0) {
            float gate = proj[(size_t)(b * L_ + t) * (2 * E_) + E_ + e];
            float gs = gate / (1.f + __expf(-gate));
            y[off] = (p + uu * Dp) * gs;
        }
    }
}

// ---------------- launch -------------------------------------------------
extern "C" void kernel_launch(void* const* d_in, const int* in_sizes, int n_in,
                              void* d_out, int out_size)
{
    const float* x      = (const float*)d_in[0];
    const float* norm_w = (const float*)d_in[1];
    const float* in_w   = (const float*)d_in[2];
    const float* conv_w = (const float*)d_in[3];
    const float* conv_b = (const float*)d_in[4];
    const float* x_w    = (const float*)d_in[5];
    const float* dt_w   = (const float*)d_in[6];
    const float* dt_b   = (const float*)d_in[7];
    const float* A_log  = (const float*)d_in[8];
    const float* Dsk    = (const float*)d_in[9];
    const float* out_w  = (const float*)d_in[10];
    const float* fin_w  = (const float*)d_in[11];
    float* out = (float*)d_out;

    float *h, *hn, *proj, *u, *ssm, *dt, *y;
    cudaGetSymbolAddress((void**)&h,    g_h);
    cudaGetSymbolAddress((void**)&hn,   g_hn);
    cudaGetSymbolAddress((void**)&proj, g_proj);
    cudaGetSymbolAddress((void**)&u,    g_u);
    cudaGetSymbolAddress((void**)&ssm,  g_ssm);
    cudaGetSymbolAddress((void**)&dt,   g_dt);
    cudaGetSymbolAddress((void**)&y,    g_y);

    cudaMemcpyAsync(h, x, sizeof(float) * ML * D_, cudaMemcpyDeviceToDevice);

    for (int l = 0; l < NL; l++) {
        rmsnorm_kernel<<<ML, 256>>>(h, norm_w + (size_t)l * D_, hn);

        // proj = hn @ in_w^T   (M=4096, N=3072, K=768)
        gemm_nt<<<dim3(2 * E_ / BN, ML / BM), 256>>>(
            hn, D_, in_w + (size_t)l * 2 * E_ * D_, D_, proj, 2 * E_,
            ML, 2 * E_, D_, 0, nullptr);

        conv_silu_kernel<<<(ML * E_ + 255) / 256, 256>>>(
            proj, conv_w + (size_t)l * E_ * K_, conv_b + (size_t)l * E_, u);

        // ssm = u @ x_w^T      (M=4096, N=80, K=1536)
        gemm_nt<<<dim3((SSMW + BN - 1) / BN, ML / BM), 256>>>(
            u, E_, x_w + (size_t)l * SSMW * E_, E_, ssm, SSMW,
            ML, SSMW, E_, 0, nullptr);

        // dt = softplus(ssm[:, :48] @ dt_w^T + dt_b)  (M=4096, N=1536, K=48)
        gemm_nt<<<dim3(E_ / BN, ML / BM), 256>>>(
            ssm, SSMW, dt_w + (size_t)l * E_ * DTR_, DTR_, dt, E_,
            ML, E_, DTR_, 1, dt_b + (size_t)l * E_);

        scan_kernel<<<(B_ * E_) / 16, 256>>>(
            dt, ssm, u, proj,
            A_log + (size_t)l * E_ * N_, Dsk + (size_t)l * E_, y);

        // h += y @ out_w^T     (M=4096, N=768, K=1536)
        gemm_nt<<<dim3(D_ / BN, ML / BM), 256>>>(
            y, E_, out_w + (size_t)l * D_ * E_, E_, h, D_,
            ML, D_, E_, 2, nullptr);
    }

    rmsnorm_kernel<<<ML, 256>>>(h, fin_w, out);
}

// round 2
// speedup vs baseline: 1.0279x; 1.0279x over previous
#include <cuda_runtime.h>
#include <math.h>
#include <stdint.h>

#define NL   8
#define D_   768
#define E_   1536
#define N_   16
#define K_   4
#define DTR_ 48
#define B_   2
#define L_   2048
#define SSMW (DTR_ + 2*N_)   /* 80 */
#define ML   (B_*L_)         /* 4096 rows */

// ---------------- static scratch (no allocations allowed) ----------------
__device__ float g_h   [ML * D_];
__device__ float g_hn  [ML * D_];
__device__ float g_proj[ML * 2 * E_];
__device__ float g_u   [ML * E_];
__device__ float g_ssm [ML * SSMW];
__device__ float g_dt  [ML * E_];
__device__ float g_y   [ML * E_];

// ---------------- RMSNorm ------------------------------------------------
__global__ void rmsnorm_kernel(const float* __restrict__ in,
                               const float* __restrict__ w,
                               float* __restrict__ out)
{
    int row = blockIdx.x;
    const float* x = in + (size_t)row * D_;
    float* o       = out + (size_t)row * D_;
    int t = threadIdx.x;               // 256 threads
    float v[3];
    float s = 0.f;
    #pragma unroll
    for (int i = 0; i < 3; i++) {
        v[i] = x[t + i * 256];
        s += v[i] * v[i];
    }
    __shared__ float red[256];
    red[t] = s;
    __syncthreads();
    #pragma unroll
    for (int off = 128; off > 0; off >>= 1) {
        if (t < off) red[t] += red[t + off];
        __syncthreads();
    }
    float scale = rsqrtf(red[0] * (1.0f / D_) + 1e-5f);
    #pragma unroll
    for (int i = 0; i < 3; i++) {
        int d = t + i * 256;
        o[d] = v[i] * scale * w[d];
    }
}

// ---------------- TF32 tensor-core NT GEMM (3xTF32 for fp32 accuracy) ----
// C[M,N] = A[M,K] * B[N,K]^T ; K % 16 == 0, M % 128 == 0.
// modes: 0 = store, 1 = softplus(acc + bias[n]), 2 = C += acc
#define BM 128
#define BN 64
#define BK 16
#define PAD 20   // smem row stride in 32-bit words (conflict-free for quad loads)

__device__ __forceinline__ uint32_t f2tf32(float x) {
    uint32_t r;
    asm("cvt.rna.tf32.f32 %0, %1;" : "=r"(r) : "f"(x));
    return r;
}

__device__ __forceinline__ void mma_tf32(float* c, const uint32_t* a, const uint32_t* b) {
    asm volatile(
        "mma.sync.aligned.m16n8k8.row.col.f32.tf32.tf32.f32 "
        "{%0,%1,%2,%3}, {%4,%5,%6,%7}, {%8,%9}, {%0,%1,%2,%3};"
        : "+f"(c[0]), "+f"(c[1]), "+f"(c[2]), "+f"(c[3])
        : "r"(a[0]), "r"(a[1]), "r"(a[2]), "r"(a[3]),
          "r"(b[0]), "r"(b[1]));
}

__global__ void __launch_bounds__(256, 2)
gemm_tf32(const float* __restrict__ A, int lda,
          const float* __restrict__ Bw, int ldb,
          float* __restrict__ C, int ldc,
          int M, int N, int Kd,
          int mode, const float* __restrict__ bias)
{
    __shared__ uint32_t AsH[BM][PAD];
    __shared__ uint32_t AsL[BM][PAD];
    __shared__ uint32_t BsH[BN][PAD];
    __shared__ uint32_t BsL[BN][PAD];

    int tid  = threadIdx.x;
    int bm   = blockIdx.y * BM;
    int bn   = blockIdx.x * BN;

    int warp = tid >> 5;
    int lane = tid & 31;
    int gid  = lane >> 2;      // 0..7
    int tig  = lane & 3;       // 0..3
    int wm   = warp & 3;       // 4 warps along M -> 32 rows each
    int wn   = warp >> 2;      // 2 warps along N -> 32 cols each

    // global staging: A rows tid/4 and tid/4+64, B row tid/4 (float4 on k)
    int ar = tid >> 2;         // 0..63
    int c4 = (tid & 3) * 4;    // 0,4,8,12

    float c[2][4][4];
    #pragma unroll
    for (int i = 0; i < 2; i++)
        #pragma unroll
        for (int j = 0; j < 4; j++)
            #pragma unroll
            for (int k = 0; k < 4; k++) c[i][j][k] = 0.f;

    int ntiles = Kd / BK;

    float4 aR0, aR1, bR;
    // prologue load (tile 0)
    {
        const float4* pa0 = (const float4*)&A[(size_t)(bm + ar) * lda + c4];
        const float4* pa1 = (const float4*)&A[(size_t)(bm + ar + 64) * lda + c4];
        aR0 = *pa0; aR1 = *pa1;
        if (bn + ar < N) bR = *(const float4*)&Bw[(size_t)(bn + ar) * ldb + c4];
        else             bR = make_float4(0.f, 0.f, 0.f, 0.f);
    }

    for (int t = 0; t < ntiles; t++) {
        // convert + store staged regs to smem
        {
            float av0[4] = {aR0.x, aR0.y, aR0.z, aR0.w};
            float av1[4] = {aR1.x, aR1.y, aR1.z, aR1.w};
            float bv [4] = {bR.x,  bR.y,  bR.z,  bR.w};
            #pragma unroll
            for (int i = 0; i < 4; i++) {
                uint32_t h0 = f2tf32(av0[i]);
                AsH[ar][c4 + i] = h0;
                AsL[ar][c4 + i] = f2tf32(av0[i] - __uint_as_float(h0));
                uint32_t h1 = f2tf32(av1[i]);
                AsH[ar + 64][c4 + i] = h1;
                AsL[ar + 64][c4 + i] = f2tf32(av1[i] - __uint_as_float(h1));
                uint32_t hb = f2tf32(bv[i]);
                BsH[ar][c4 + i] = hb;
                BsL[ar][c4 + i] = f2tf32(bv[i] - __uint_as_float(hb));
            }
        }
        __syncthreads();

        // prefetch next tile
        if (t + 1 < ntiles) {
            int k0 = (t + 1) * BK;
            aR0 = *(const float4*)&A[(size_t)(bm + ar) * lda + k0 + c4];
            aR1 = *(const float4*)&A[(size_t)(bm + ar + 64) * lda + k0 + c4];
            if (bn + ar < N) bR = *(const float4*)&Bw[(size_t)(bn + ar) * ldb + k0 + c4];
            else             bR = make_float4(0.f, 0.f, 0.f, 0.f);
        }

        // compute: 2 k-steps of 8
        #pragma unroll
        for (int kk = 0; kk < BK; kk += 8) {
            uint32_t ah[2][4], al[2][4], bh[4][2], bl[4][2];
            #pragma unroll
            for (int mt = 0; mt < 2; mt++) {
                int r = wm * 32 + mt * 16 + gid;
                ah[mt][0] = AsH[r    ][kk + tig];
                ah[mt][1] = AsH[r + 8][kk + tig];
                ah[mt][2] = AsH[r    ][kk + tig + 4];
                ah[mt][3] = AsH[r + 8][kk + tig + 4];
                al[mt][0] = AsL[r    ][kk + tig];
                al[mt][1] = AsL[r + 8][kk + tig];
                al[mt][2] = AsL[r    ][kk + tig + 4];
                al[mt][3] = AsL[r + 8][kk + tig + 4];
            }
            #pragma unroll
            for (int nt = 0; nt < 4; nt++) {
                int cn = wn * 32 + nt * 8 + gid;
                bh[nt][0] = BsH[cn][kk + tig];
                bh[nt][1] = BsH[cn][kk + tig + 4];
                bl[nt][0] = BsL[cn][kk + tig];
                bl[nt][1] = BsL[cn][kk + tig + 4];
            }
            #pragma unroll
            for (int mt = 0; mt < 2; mt++)
                #pragma unroll
                for (int nt = 0; nt < 4; nt++) {
                    mma_tf32(c[mt][nt], ah[mt], bh[nt]);
                    mma_tf32(c[mt][nt], al[mt], bh[nt]);
                    mma_tf32(c[mt][nt], ah[mt], bl[nt]);
                }
        }
        __syncthreads();
    }

    // epilogue
    #pragma unroll
    for (int mt = 0; mt < 2; mt++) {
        #pragma unroll
        for (int nt = 0; nt < 4; nt++) {
            int r0 = bm + wm * 32 + mt * 16 + gid;
            int cn = bn + wn * 32 + nt * 8 + tig * 2;
            #pragma unroll
            for (int k = 0; k < 4; k++) {
                int r = r0 + (k >> 1) * 8;
                int cc = cn + (k & 1);
                if (cc >= N) continue;
                float v = c[mt][nt][k];
                size_t off = (size_t)r * ldc + cc;
                if (mode == 1) {
                    v += bias[cc];
                    v = (v > 20.f) ? v : log1pf(__expf(v));
                    C[off] = v;
                } else if (mode == 2) {
                    C[off] += v;
                } else {
                    C[off] = v;
                }
            }
        }
    }
}

// ---------------- causal depthwise conv (K=4) + SiLU ---------------------
__global__ void conv_silu_kernel(const float* __restrict__ proj,
                                 const float* __restrict__ cw,
                                 const float* __restrict__ cb,
                                 float* __restrict__ u)
{
    int idx = blockIdx.x * blockDim.x + threadIdx.x;
    if (idx >= ML * E_) return;
    int e = idx % E_;
    int r = idx / E_;
    int l = r % L_;
    float acc = cb[e];
    #pragma unroll
    for (int j = 0; j < K_; j++) {
        int t = l - (K_ - 1) + j;
        if (t >= 0)
            acc += proj[(size_t)(r - (K_ - 1) + j) * (2 * E_) + e] * cw[e * K_ + j];
    }
    u[idx] = acc / (1.f + __expf(-acc));
}

// ---------------- selective scan: 16-lane group per (b,e) ----------------
__global__ void scan_kernel(const float* __restrict__ dtb,
                            const float* __restrict__ ssm,
                            const float* __restrict__ ub,
                            const float* __restrict__ proj,
                            const float* __restrict__ A_log,
                            const float* __restrict__ Dsk,
                            float* __restrict__ y)
{
    int g = blockIdx.x * (blockDim.x / 16) + (threadIdx.x / 16);
    int lane = threadIdx.x & 15;
    if (g >= B_ * E_) return;
    int b = g / E_;
    int e = g % E_;

    float A  = -__expf(A_log[e * N_ + lane]);
    float Dp = Dsk[e];
    float s  = 0.f;

    size_t base_be = (size_t)b * L_ * E_ + e;
    size_t base_bs = (size_t)b * L_ * SSMW;

    for (int t = 0; t < L_; t++) {
        size_t off = base_be + (size_t)t * E_;
        float dt = dtb[off];
        float uu = ub[off];
        const float* sp = ssm + base_bs + (size_t)t * SSMW;
        float Bv = sp[DTR_ + lane];
        float Cv = sp[DTR_ + N_ + lane];

        float dA = __expf(dt * A);
        s = s * dA + dt * Bv * uu;

        float p = s * Cv;
        p += __shfl_xor_sync(0xffffffffu, p, 8, 16);
        p += __shfl_xor_sync(0xffffffffu, p, 4, 16);
        p += __shfl_xor_sync(0xffffffffu, p, 2, 16);
        p += __shfl_xor_sync(0xffffffffu, p, 1, 16);

        if (lane == 0) {
            float gate = proj[(size_t)(b * L_ + t) * (2 * E_) + E_ + e];
            float gs = gate / (1.f + __expf(-gate));
            y[off] = (p + uu * Dp) * gs;
        }
    }
}

// ---------------- launch -------------------------------------------------
extern "C" void kernel_launch(void* const* d_in, const int* in_sizes, int n_in,
                              void* d_out, int out_size)
{
    const float* x      = (const float*)d_in[0];
    const float* norm_w = (const float*)d_in[1];
    const float* in_w   = (const float*)d_in[2];
    const float* conv_w = (const float*)d_in[3];
    const float* conv_b = (const float*)d_in[4];
    const float* x_w    = (const float*)d_in[5];
    const float* dt_w   = (const float*)d_in[6];
    const float* dt_b   = (const float*)d_in[7];
    const float* A_log  = (const float*)d_in[8];
    const float* Dsk    = (const float*)d_in[9];
    const float* out_w  = (const float*)d_in[10];
    const float* fin_w  = (const float*)d_in[11];
    float* out = (float*)d_out;

    float *h, *hn, *proj, *u, *ssm, *dt, *y;
    cudaGetSymbolAddress((void**)&h,    g_h);
    cudaGetSymbolAddress((void**)&hn,   g_hn);
    cudaGetSymbolAddress((void**)&proj, g_proj);
    cudaGetSymbolAddress((void**)&u,    g_u);
    cudaGetSymbolAddress((void**)&ssm,  g_ssm);
    cudaGetSymbolAddress((void**)&dt,   g_dt);
    cudaGetSymbolAddress((void**)&y,    g_y);

    cudaMemcpyAsync(h, x, sizeof(float) * ML * D_, cudaMemcpyDeviceToDevice);

    for (int l = 0; l < NL; l++) {
        rmsnorm_kernel<<<ML, 256>>>(h, norm_w + (size_t)l * D_, hn);

        // proj = hn @ in_w^T   (M=4096, N=3072, K=768)
        gemm_tf32<<<dim3(2 * E_ / BN, ML / BM), 256>>>(
            hn, D_, in_w + (size_t)l * 2 * E_ * D_, D_, proj, 2 * E_,
            ML, 2 * E_, D_, 0, nullptr);

        conv_silu_kernel<<<(ML * E_ + 255) / 256, 256>>>(
            proj, conv_w + (size_t)l * E_ * K_, conv_b + (size_t)l * E_, u);

        // ssm = u @ x_w^T      (M=4096, N=80, K=1536)
        gemm_tf32<<<dim3((SSMW + BN - 1) / BN, ML / BM), 256>>>(
            u, E_, x_w + (size_t)l * SSMW * E_, E_, ssm, SSMW,
            ML, SSMW, E_, 0, nullptr);

        // dt = softplus(ssm[:, :48] @ dt_w^T + dt_b)  (M=4096, N=1536, K=48)
        gemm_tf32<<<dim3(E_ / BN, ML / BM), 256>>>(
            ssm, SSMW, dt_w + (size_t)l * E_ * DTR_, DTR_, dt, E_,
            ML, E_, DTR_, 1, dt_b + (size_t)l * E_);

        scan_kernel<<<(B_ * E_) / 16, 256>>>(
            dt, ssm, u, proj,
            A_log + (size_t)l * E_ * N_, Dsk + (size_t)l * E_, y);

        // h += y @ out_w^T     (M=4096, N=768, K=1536)
        gemm_tf32<<<dim3(D_ / BN, ML / BM), 256>>>(
            y, E_, out_w + (size_t)l * D_ * E_, E_, h, D_,
            ML, D_, E_, 2, nullptr);
    }

    rmsnorm_kernel<<<ML, 256>>>(h, fin_w, out);
}

// round 3
// speedup vs baseline: 1.0966x; 1.0669x over previous
#include <cuda_runtime.h>
#include <math.h>
#include <stdint.h>

#define NL   8
#define D_   768
#define E_   1536
#define N_   16
#define K_   4
#define DTR_ 48
#define B_   2
#define L_   2048
#define SSMW (DTR_ + 2*N_)   /* 80 */
#define ML   (B_*L_)         /* 4096 rows */

// ---------------- static scratch (no allocations allowed) ----------------
__device__ float g_h   [ML * D_];
__device__ float g_hn  [ML * D_];
__device__ float g_proj[ML * 2 * E_];
__device__ float g_u   [ML * E_];
__device__ float g_ssm [ML * SSMW];
__device__ float g_dt  [ML * E_];
__device__ float g_y   [ML * E_];

// ---------------- RMSNorm ------------------------------------------------
__global__ void rmsnorm_kernel(const float* __restrict__ in,
                               const float* __restrict__ w,
                               float* __restrict__ out)
{
    int row = blockIdx.x;
    const float* x = in + (size_t)row * D_;
    float* o       = out + (size_t)row * D_;
    int t = threadIdx.x;               // 256 threads
    float v[3];
    float s = 0.f;
    #pragma unroll
    for (int i = 0; i < 3; i++) {
        v[i] = x[t + i * 256];
        s += v[i] * v[i];
    }
    __shared__ float red[256];
    red[t] = s;
    __syncthreads();
    #pragma unroll
    for (int off = 128; off > 0; off >>= 1) {
        if (t < off) red[t] += red[t + off];
        __syncthreads();
    }
    float scale = rsqrtf(red[0] * (1.0f / D_) + 1e-5f);
    #pragma unroll
    for (int i = 0; i < 3; i++) {
        int d = t + i * 256;
        o[d] = v[i] * scale * w[d];
    }
}

// ---------------- TF32 3x tensor GEMM, cp.async pipelined ----------------
// C[M,N] = A[M,K] * B[N,K]^T ; K%16==0, M%128==0.
// modes: 0 = store, 1 = softplus(acc + bias[n]), 2 = C += acc
#define BM 128
#define BN 64
#define BK 16
#define STG 3
#define SP 20   // smem row stride (floats): conflict-free frag reads, 16B aligned

__device__ __forceinline__ uint32_t f2tf32(float x) {
    uint32_t r;
    asm("cvt.rna.tf32.f32 %0, %1;" : "=r"(r) : "f"(x));
    return r;
}

__device__ __forceinline__ void hilo(float x, uint32_t& h, uint32_t& l) {
    h = f2tf32(x);
    l = f2tf32(x - __uint_as_float(h));
}

__device__ __forceinline__ void mma_tf32(float* c, const uint32_t* a, const uint32_t* b) {
    asm volatile(
        "mma.sync.aligned.m16n8k8.row.col.f32.tf32.tf32.f32 "
        "{%0,%1,%2,%3}, {%4,%5,%6,%7}, {%8,%9}, {%0,%1,%2,%3};"
        : "+f"(c[0]), "+f"(c[1]), "+f"(c[2]), "+f"(c[3])
        : "r"(a[0]), "r"(a[1]), "r"(a[2]), "r"(a[3]),
          "r"(b[0]), "r"(b[1]));
}

__device__ __forceinline__ void cp16(float* dst_smem, const float* src, bool pred) {
    uint32_t d = (uint32_t)__cvta_generic_to_shared(dst_smem);
    int sz = pred ? 16 : 0;
    asm volatile("cp.async.cg.shared.global [%0], [%1], 16, %2;"
                 :: "r"(d), "l"(src), "r"(sz));
}

__global__ void __launch_bounds__(256, 2)
gemm_tf32(const float* __restrict__ A, int lda,
          const float* __restrict__ Bw, int ldb,
          float* __restrict__ C, int ldc,
          int M, int N, int Kd,
          int mode, const float* __restrict__ bias)
{
    __shared__ float As[STG][BM][SP];
    __shared__ float Bs[STG][BN][SP];

    int tid  = threadIdx.x;
    int bm   = blockIdx.y * BM;
    int bn   = blockIdx.x * BN;

    int warp = tid >> 5;
    int lane = tid & 31;
    int gid  = lane >> 2;      // 0..7
    int tig  = lane & 3;       // 0..3
    int wm   = warp & 3;       // 4 warps along M -> 32 rows each
    int wn   = warp >> 2;      // 2 warps along N -> 32 cols each

    // cp.async mapping: 16B chunks over k
    int ar0 = tid >> 2;             // 0..63
    int ac  = (tid & 3) * 4;        // 0,4,8,12

    int ntiles = Kd / BK;

    float acc[2][4][4];
    #pragma unroll
    for (int i = 0; i < 2; i++)
        #pragma unroll
        for (int j = 0; j < 4; j++)
            #pragma unroll
            for (int k = 0; k < 4; k++) acc[i][j][k] = 0.f;

    // issue loads for tile t into stage s
    auto issue = [&](int s, int t) {
        int k0 = t * BK;
        cp16(&As[s][ar0     ][ac], &A[(size_t)(bm + ar0     ) * lda + k0 + ac], true);
        cp16(&As[s][ar0 + 64][ac], &A[(size_t)(bm + ar0 + 64) * lda + k0 + ac], true);
        cp16(&Bs[s][ar0][ac], &Bw[(size_t)(bn + ar0) * ldb + k0 + ac], (bn + ar0) < N);
    };

    // prologue: stages 0..STG-2
    #pragma unroll
    for (int s = 0; s < STG - 1; s++) {
        if (s < ntiles) issue(s, s);
        asm volatile("cp.async.commit_group;");
    }

    for (int t = 0; t < ntiles; t++) {
        asm volatile("cp.async.wait_group %0;" :: "n"(STG - 2));
        __syncthreads();

        int tn = t + STG - 1;
        if (tn < ntiles) issue(tn % STG, tn);
        asm volatile("cp.async.commit_group;");

        int s = t % STG;
        #pragma unroll
        for (int kk = 0; kk < BK; kk += 8) {
            uint32_t ah[2][4], al[2][4];
            #pragma unroll
            for (int mt = 0; mt < 2; mt++) {
                int r = wm * 32 + mt * 16 + gid;
                float x0 = As[s][r    ][kk + tig];
                float x1 = As[s][r + 8][kk + tig];
                float x2 = As[s][r    ][kk + tig + 4];
                float x3 = As[s][r + 8][kk + tig + 4];
                hilo(x0, ah[mt][0], al[mt][0]);
                hilo(x1, ah[mt][1], al[mt][1]);
                hilo(x2, ah[mt][2], al[mt][2]);
                hilo(x3, ah[mt][3], al[mt][3]);
            }
            uint32_t bh[4][2], bl[4][2];
            #pragma unroll
            for (int nt = 0; nt < 4; nt++) {
                int cn = wn * 32 + nt * 8 + gid;
                float y0 = Bs[s][cn][kk + tig];
                float y1 = Bs[s][cn][kk + tig + 4];
                hilo(y0, bh[nt][0], bl[nt][0]);
                hilo(y1, bh[nt][1], bl[nt][1]);
            }
            #pragma unroll
            for (int mt = 0; mt < 2; mt++)
                #pragma unroll
                for (int nt = 0; nt < 4; nt++) {
                    mma_tf32(acc[mt][nt], ah[mt], bh[nt]);
                    mma_tf32(acc[mt][nt], al[mt], bh[nt]);
                    mma_tf32(acc[mt][nt], ah[mt], bl[nt]);
                }
        }
        __syncthreads();
    }

    // epilogue
    #pragma unroll
    for (int mt = 0; mt < 2; mt++) {
        #pragma unroll
        for (int nt = 0; nt < 4; nt++) {
            int r0 = bm + wm * 32 + mt * 16 + gid;
            int cn = bn + wn * 32 + nt * 8 + tig * 2;
            #pragma unroll
            for (int k = 0; k < 4; k++) {
                int r  = r0 + (k >> 1) * 8;
                int cc = cn + (k & 1);
                if (cc >= N) continue;
                float v = acc[mt][nt][k];
                size_t off = (size_t)r * ldc + cc;
                if (mode == 1) {
                    v += bias[cc];
                    v = (v > 20.f) ? v : log1pf(__expf(v));
                    C[off] = v;
                } else if (mode == 2) {
                    C[off] += v;
                } else {
                    C[off] = v;
                }
            }
        }
    }
}

// ---------------- causal depthwise conv (K=4) + SiLU ---------------------
__global__ void conv_silu_kernel(const float* __restrict__ proj,
                                 const float* __restrict__ cw,
                                 const float* __restrict__ cb,
                                 float* __restrict__ u)
{
    int idx = blockIdx.x * blockDim.x + threadIdx.x;
    if (idx >= ML * E_) return;
    int e = idx % E_;
    int r = idx / E_;
    int l = r % L_;
    float acc = cb[e];
    #pragma unroll
    for (int j = 0; j < K_; j++) {
        int t = l - (K_ - 1) + j;
        if (t >= 0)
            acc += proj[(size_t)(r - (K_ - 1) + j) * (2 * E_) + e] * cw[e * K_ + j];
    }
    u[idx] = acc / (1.f + __expf(-acc));
}

// ---------------- selective scan: 16-lane group per (b,e) ----------------
__global__ void scan_kernel(const float* __restrict__ dtb,
                            const float* __restrict__ ssm,
                            const float* __restrict__ ub,
                            const float* __restrict__ proj,
                            const float* __restrict__ A_log,
                            const float* __restrict__ Dsk,
                            float* __restrict__ y)
{
    int g = blockIdx.x * (blockDim.x / 16) + (threadIdx.x / 16);
    int lane = threadIdx.x & 15;
    if (g >= B_ * E_) return;
    int b = g / E_;
    int e = g % E_;

    float A  = -__expf(A_log[e * N_ + lane]);
    float Dp = Dsk[e];
    float s  = 0.f;

    size_t base_be = (size_t)b * L_ * E_ + e;
    size_t base_bs = (size_t)b * L_ * SSMW;

    for (int t = 0; t < L_; t++) {
        size_t off = base_be + (size_t)t * E_;
        float dt = dtb[off];
        float uu = ub[off];
        const float* sp = ssm + base_bs + (size_t)t * SSMW;
        float Bv = sp[DTR_ + lane];
        float Cv = sp[DTR_ + N_ + lane];

        float dA = __expf(dt * A);
        s = s * dA + dt * Bv * uu;

        float p = s * Cv;
        p += __shfl_xor_sync(0xffffffffu, p, 8, 16);
        p += __shfl_xor_sync(0xffffffffu, p, 4, 16);
        p += __shfl_xor_sync(0xffffffffu, p, 2, 16);
        p += __shfl_xor_sync(0xffffffffu, p, 1, 16);

        if (lane == 0) {
            float gate = proj[(size_t)(b * L_ + t) * (2 * E_) + E_ + e];
            float gs = gate / (1.f + __expf(-gate));
            y[off] = (p + uu * Dp) * gs;
        }
    }
}

// ---------------- launch -------------------------------------------------
extern "C" void kernel_launch(void* const* d_in, const int* in_sizes, int n_in,
                              void* d_out, int out_size)
{
    const float* x      = (const float*)d_in[0];
    const float* norm_w = (const float*)d_in[1];
    const float* in_w   = (const float*)d_in[2];
    const float* conv_w = (const float*)d_in[3];
    const float* conv_b = (const float*)d_in[4];
    const float* x_w    = (const float*)d_in[5];
    const float* dt_w   = (const float*)d_in[6];
    const float* dt_b   = (const float*)d_in[7];
    const float* A_log  = (const float*)d_in[8];
    const float* Dsk    = (const float*)d_in[9];
    const float* out_w  = (const float*)d_in[10];
    const float* fin_w  = (const float*)d_in[11];
    float* out = (float*)d_out;

    float *h, *hn, *proj, *u, *ssm, *dt, *y;
    cudaGetSymbolAddress((void**)&h,    g_h);
    cudaGetSymbolAddress((void**)&hn,   g_hn);
    cudaGetSymbolAddress((void**)&proj, g_proj);
    cudaGetSymbolAddress((void**)&u,    g_u);
    cudaGetSymbolAddress((void**)&ssm,  g_ssm);
    cudaGetSymbolAddress((void**)&dt,   g_dt);
    cudaGetSymbolAddress((void**)&y,    g_y);

    cudaMemcpyAsync(h, x, sizeof(float) * ML * D_, cudaMemcpyDeviceToDevice);

    for (int l = 0; l < NL; l++) {
        rmsnorm_kernel<<<ML, 256>>>(h, norm_w + (size_t)l * D_, hn);

        // proj = hn @ in_w^T   (M=4096, N=3072, K=768)
        gemm_tf32<<<dim3(2 * E_ / BN, ML / BM), 256>>>(
            hn, D_, in_w + (size_t)l * 2 * E_ * D_, D_, proj, 2 * E_,
            ML, 2 * E_, D_, 0, nullptr);

        conv_silu_kernel<<<(ML * E_ + 255) / 256, 256>>>(
            proj, conv_w + (size_t)l * E_ * K_, conv_b + (size_t)l * E_, u);

        // ssm = u @ x_w^T      (M=4096, N=80, K=1536)
        gemm_tf32<<<dim3((SSMW + BN - 1) / BN, ML / BM), 256>>>(
            u, E_, x_w + (size_t)l * SSMW * E_, E_, ssm, SSMW,
            ML, SSMW, E_, 0, nullptr);

        // dt = softplus(ssm[:, :48] @ dt_w^T + dt_b)  (M=4096, N=1536, K=48)
        gemm_tf32<<<dim3(E_ / BN, ML / BM), 256>>>(
            ssm, SSMW, dt_w + (size_t)l * E_ * DTR_, DTR_, dt, E_,
            ML, E_, DTR_, 1, dt_b + (size_t)l * E_);

        scan_kernel<<<(B_ * E_) / 16, 256>>>(
            dt, ssm, u, proj,
            A_log + (size_t)l * E_ * N_, Dsk + (size_t)l * E_, y);

        // h += y @ out_w^T     (M=4096, N=768, K=1536)
        gemm_tf32<<<dim3(D_ / BN, ML / BM), 256>>>(
            y, E_, out_w + (size_t)l * D_ * E_, E_, h, D_,
            ML, D_, E_, 2, nullptr);
    }

    rmsnorm_kernel<<<ML, 256>>>(h, fin_w, out);
}